// round 11
// baseline (speedup 1.0000x reference)
#include <cuda_runtime.h>
#include <cuda_bf16.h>
#include <cuda_fp8.h>
#include <math.h>

#define MAXN 50048
#define MAXE 800000
#define MAXT (MAXE + MAXN)
#define SCAN_CHUNK 1024
#define EA_SCALE 268435456.0f   // 2^28

// ---- scratch (static __device__, no allocations) ----
__device__ __align__(16) unsigned char g_xw1f8[MAXN * 256];
__device__ __align__(16) float g_als1[MAXN * 4];
__device__ __align__(16) float g_ald1[MAXN * 4];
__device__ unsigned long long g_dl[MAXN];   // (count<<40) | fixed-point ea sum
__device__ int   g_off[MAXN + 1];
__device__ int   g_cur[MAXN];
__device__ __align__(16)  int2  g_slot[MAXT];    // (src, ea-bits) per adjacency slot
__device__ int   g_bsum[64];
__device__ __align__(16) __nv_bfloat16 g_h1b[MAXN * 256];
__device__ __align__(16) __nv_bfloat16 g_xw2b[MAXN * 64];
__device__ float g_als2[MAXN];
__device__ float g_ald2[MAXN];
__device__ float g_ce[5];
__device__ float g_pool[264];   // [0:256) zsum[4][64], [256:260) cnt, [260:264) cf

__device__ __forceinline__ float lrelu(float x) { return x > 0.f ? x : 0.2f * x; }
__device__ __forceinline__ float eluf(float x)  { return x > 0.f ? x : (expf(x) - 1.f); }

__device__ __forceinline__ float2 f8x2tof2(unsigned short v) {
    __half2_raw hr = __nv_cvt_fp8x2_to_halfraw2((__nv_fp8x2_storage_t)v, __NV_E4M3);
    return __half22float2(*reinterpret_cast<__half2*>(&hr));
}
__device__ __forceinline__ unsigned short f2tof8x2(float a, float b) {
    return (unsigned short)__nv_cvt_float2_to_fp8x2(make_float2(a, b),
                                                    __NV_SATFINITE, __NV_E4M3);
}

// packed dual-fp32 FMA (B300 f32x2 pipe; PTX-only form)
__device__ __forceinline__ void ffma2(float2& d, const float2 a, const float2 b) {
    unsigned long long aa, bb;
    memcpy(&aa, &a, 8);
    memcpy(&bb, &b, 8);
    unsigned long long& dd = reinterpret_cast<unsigned long long&>(d);
    asm("fma.rn.f32x2 %0, %1, %2, %0;" : "+l"(dd) : "l"(aa), "l"(bb));
}

// ---- degree+ea-sum (single packed 64-bit atomic) + cluster cnt/cf + ce ----
__global__ void k_degloop(const int* __restrict__ dst, const float* __restrict__ ea,
                          const float* __restrict__ x, const int* __restrict__ assign,
                          const float* __restrict__ We1, const float* __restrict__ ae1,
                          const float* __restrict__ We2, const float* __restrict__ ae2,
                          int e, int n) {
    __shared__ float s8[8];
    int t = threadIdx.x;
    if (t < 8) s8[t] = 0.f;
    __syncthreads();
    int idx = blockIdx.x * blockDim.x + t;
    if (idx < e) {
        int d = dst[idx];
        unsigned long long pk = (1ULL << 40) |
            (unsigned long long)(unsigned int)__float2uint_rn(ea[idx] * EA_SCALE);
        atomicAdd(&g_dl[d], pk);
    } else if (idx < e + n) {
        int node = idx - e;
        atomicAdd(&g_dl[node], 1ULL << 40);
        int a = assign[node];
        atomicAdd(&s8[a], 1.f);
        atomicAdd(&s8[4 + a], x[node * 7 + 6]);
    }
    if (blockIdx.x == 0) {
        __shared__ float s5[5];
        if (t < 5) s5[t] = 0.f;
        __syncthreads();
        atomicAdd(&s5[t >> 6], We1[t] * ae1[t]);
        if (t < 64) atomicAdd(&s5[4], We2[t] * ae2[t]);
        __syncthreads();
        if (t < 5) g_ce[t] = s5[t];
    }
    __syncthreads();
    if (t < 8 && s8[t] != 0.f) atomicAdd(&g_pool[256 + t], s8[t]);
}

// ---- scan stage 1: per-block sums (256 thr x 4 elems = 1024/block) ----
__global__ void k_part(int n) {
    int t = threadIdx.x;
    int base = blockIdx.x * SCAN_CHUNK + t * 4;
    int s = 0;
#pragma unroll
    for (int i = 0; i < 4; i++) {
        int idx = base + i;
        if (idx < n) s += (int)(g_dl[idx] >> 40);
    }
#pragma unroll
    for (int o = 16; o; o >>= 1) s += __shfl_down_sync(0xffffffffu, s, o);
    __shared__ int ws[8];
    if ((t & 31) == 0) ws[t >> 5] = s;
    __syncthreads();
    if (t < 8) {
        int v = ws[t];
#pragma unroll
        for (int o = 4; o; o >>= 1) v += __shfl_down_sync(0xffu, v, o);
        if (t == 0) g_bsum[blockIdx.x] = v;
    }
}

// ---- scan stage 2: block-local scan + inline 64-wide scan of block sums ----
__global__ void k_offs(int n, int tot, int nb) {
    int t = threadIdx.x;                      // 256 threads
    __shared__ int spre[64];
    __shared__ int w0tot;
    if (t < 64) {
        int s = (t < nb) ? g_bsum[t] : 0;
        int lane = t & 31;
        int v = s;
#pragma unroll
        for (int o = 1; o < 32; o <<= 1) {
            int u = __shfl_up_sync(0xffffffffu, v, o);
            if (lane >= o) v += u;
        }
        if (t == 31) w0tot = v;
        spre[t] = v - s;                      // warp-local exclusive; fix warp1 below
    }
    __syncthreads();
    if (t >= 32 && t < 64) spre[t] += w0tot;
    int base = blockIdx.x * SCAN_CHUNK + t * 4;
    int v[4];
    int s = 0;
#pragma unroll
    for (int i = 0; i < 4; i++) {
        int idx = base + i;
        v[i] = (idx < n) ? (int)(g_dl[idx] >> 40) : 0;
        s += v[i];
    }
    int lane = t & 31, w = t >> 5;
    int ps = s;
#pragma unroll
    for (int o = 1; o < 32; o <<= 1) {
        int u = __shfl_up_sync(0xffffffffu, ps, o);
        if (lane >= o) ps += u;
    }
    __shared__ int ws[8];
    if (lane == 31) ws[w] = ps;
    __syncthreads();
    if (t < 8) {
        int x = ws[t];
#pragma unroll
        for (int o = 1; o < 8; o <<= 1) {
            int u = __shfl_up_sync(0xffu, x, o);
            if (t >= o) x += u;
        }
        ws[t] = x;
    }
    __syncthreads();
    int excl = ps - s + (w ? ws[w - 1] : 0) + spre[blockIdx.x];
#pragma unroll
    for (int i = 0; i < 4; i++) {
        int idx = base + i;
        if (idx < n) {
            g_off[idx] = excl;
            g_cur[idx] = excl;
            excl += v[i];
        }
    }
    if (blockIdx.x == 0 && t == 0) g_off[n] = tot;
}

// ---- xw1 = x @ W1 (+ fused al_src1 / al_dst1), one warp per node, fp8 store ----
__global__ void k_xw1(const float* __restrict__ x, const float* __restrict__ W1,
                      const float* __restrict__ as1, const float* __restrict__ ad1, int n) {
    __shared__ float sW[7 * 256];
    __shared__ float sA[256];
    __shared__ float sB[256];
    int t = threadIdx.x;
    for (int i = t; i < 7 * 256; i += blockDim.x) sW[i] = W1[i];
    if (t < 256) { sA[t] = as1[t]; sB[t] = ad1[t]; }
    __syncthreads();
    int node = (blockIdx.x * blockDim.x + t) >> 5;
    int lane = t & 31;
    if (node >= n) return;
    float xv[7];
#pragma unroll
    for (int i = 0; i < 7; i++) xv[i] = x[node * 7 + i];
    const float2* sW2 = reinterpret_cast<const float2*>(sW);
    const float2* sA2 = reinterpret_cast<const float2*>(sA);
    const float2* sB2 = reinterpret_cast<const float2*>(sB);
    float accs[4], accd[4];
    unsigned short* ob = reinterpret_cast<unsigned short*>(g_xw1f8 + (size_t)node * 256);
#pragma unroll
    for (int k = 0; k < 4; k++) {
        int p = k * 32 + lane;                 // pair index within 128-wide row
        float v0 = 0.f, v1 = 0.f;
#pragma unroll
        for (int i = 0; i < 7; i++) {
            float2 wv = sW2[i * 128 + p];
            v0 = fmaf(xv[i], wv.x, v0);
            v1 = fmaf(xv[i], wv.y, v1);
        }
        float2 av = sA2[p], bv = sB2[p];
        accs[k] = fmaf(v0, av.x, v1 * av.y);
        accd[k] = fmaf(v0, bv.x, v1 * bv.y);
        ob[p] = f2tof8x2(v0, v1);
    }
#pragma unroll
    for (int h = 0; h < 4; h++) {
        float vs = accs[h], vd = accd[h];
#pragma unroll
        for (int o = 16; o; o >>= 1) {
            vs += __shfl_down_sync(0xffffffffu, vs, o);
            vd += __shfl_down_sync(0xffffffffu, vd, o);
        }
        if (lane == 0) { g_als1[node * 4 + h] = vs; g_ald1[node * 4 + h] = vd; }
    }
}

// ---- fill adjacency; self-loop threads decode a and re-zero g_dl for next run ----
__global__ void k_fill(const int* __restrict__ src, const int* __restrict__ dst,
                       const float* __restrict__ ea, int e, int n) {
    int idx = blockIdx.x * blockDim.x + threadIdx.x;
    if (idx >= e + n) return;
    int d, s; float a;
    if (idx < e) { d = dst[idx]; s = src[idx]; a = ea[idx]; }
    else {
        d = idx - e; s = d;
        unsigned long long v = g_dl[d];
        float cnt = (float)(int)((v >> 40) - 1ULL);
        float sum = (float)(v & ((1ULL << 40) - 1ULL)) * (1.0f / EA_SCALE);
        a = sum / fmaxf(cnt, 1.f);
        g_dl[d] = 0ULL;          // cleanup for next launch
    }
    int p = atomicAdd(&g_cur[d], 1);
    g_slot[p] = make_int2(s, __float_as_int(a));
}

// ---- conv1 gather-aggregate, 32 thr/node, fp8 rows, int4 slot pairs ----
__global__ void k_gather1(const float* __restrict__ b1, int n) {
    int gt = blockIdx.x * blockDim.x + threadIdx.x;
    int node = gt >> 5;
    if (node >= n) return;
    int l = gt & 31, h = l >> 3;
    int beg = g_off[node], end = g_off[node + 1];
    float ald_h = g_ald1[node * 4 + h];
    float ce_h = g_ce[h];
    float a0 = 0, a1 = 0, a2 = 0, a3 = 0, a4 = 0, a5 = 0, a6 = 0, a7 = 0;
    float c0 = 0, c1 = 0, c2 = 0, c3 = 0, c4 = 0, c5 = 0, c6 = 0, c7 = 0;
    float swa = 0.f, swb = 0.f;
    int i = beg;
    // peel to 16B-aligned pair boundary
    if ((i & 1) && i < end) {
        int2 sd = g_slot[i];
        float lg = g_als1[sd.x * 4 + h] + ald_h + __int_as_float(sd.y) * ce_h;
        float w = __expf(lrelu(lg));
        uint2 raw = *reinterpret_cast<const uint2*>(g_xw1f8 + (size_t)sd.x * 256 + l * 8);
        float2 p0 = f8x2tof2((unsigned short)(raw.x & 0xffffu));
        float2 p1 = f8x2tof2((unsigned short)(raw.x >> 16));
        float2 p2 = f8x2tof2((unsigned short)(raw.y & 0xffffu));
        float2 p3 = f8x2tof2((unsigned short)(raw.y >> 16));
        a0 = fmaf(w, p0.x, a0); a1 = fmaf(w, p0.y, a1);
        a2 = fmaf(w, p1.x, a2); a3 = fmaf(w, p1.y, a3);
        a4 = fmaf(w, p2.x, a4); a5 = fmaf(w, p2.y, a5);
        a6 = fmaf(w, p3.x, a6); a7 = fmaf(w, p3.y, a7);
        swa += w;
        i++;
    }
    for (; i + 2 <= end; i += 2) {
        int4 ss = *reinterpret_cast<const int4*>(&g_slot[i]);
        float lgA = g_als1[ss.x * 4 + h] + ald_h + __int_as_float(ss.y) * ce_h;
        float lgB = g_als1[ss.z * 4 + h] + ald_h + __int_as_float(ss.w) * ce_h;
        uint2 rA = *reinterpret_cast<const uint2*>(g_xw1f8 + (size_t)ss.x * 256 + l * 8);
        uint2 rB = *reinterpret_cast<const uint2*>(g_xw1f8 + (size_t)ss.z * 256 + l * 8);
        float wA = __expf(lrelu(lgA));
        float wB = __expf(lrelu(lgB));
        float2 pA0 = f8x2tof2((unsigned short)(rA.x & 0xffffu));
        float2 pA1 = f8x2tof2((unsigned short)(rA.x >> 16));
        float2 pA2 = f8x2tof2((unsigned short)(rA.y & 0xffffu));
        float2 pA3 = f8x2tof2((unsigned short)(rA.y >> 16));
        float2 pB0 = f8x2tof2((unsigned short)(rB.x & 0xffffu));
        float2 pB1 = f8x2tof2((unsigned short)(rB.x >> 16));
        float2 pB2 = f8x2tof2((unsigned short)(rB.y & 0xffffu));
        float2 pB3 = f8x2tof2((unsigned short)(rB.y >> 16));
        a0 = fmaf(wA, pA0.x, a0); a1 = fmaf(wA, pA0.y, a1);
        a2 = fmaf(wA, pA1.x, a2); a3 = fmaf(wA, pA1.y, a3);
        a4 = fmaf(wA, pA2.x, a4); a5 = fmaf(wA, pA2.y, a5);
        a6 = fmaf(wA, pA3.x, a6); a7 = fmaf(wA, pA3.y, a7);
        c0 = fmaf(wB, pB0.x, c0); c1 = fmaf(wB, pB0.y, c1);
        c2 = fmaf(wB, pB1.x, c2); c3 = fmaf(wB, pB1.y, c3);
        c4 = fmaf(wB, pB2.x, c4); c5 = fmaf(wB, pB2.y, c5);
        c6 = fmaf(wB, pB3.x, c6); c7 = fmaf(wB, pB3.y, c7);
        swa += wA; swb += wB;
    }
    if (i < end) {
        int2 sd = g_slot[i];
        float lg = g_als1[sd.x * 4 + h] + ald_h + __int_as_float(sd.y) * ce_h;
        float w = __expf(lrelu(lg));
        uint2 raw = *reinterpret_cast<const uint2*>(g_xw1f8 + (size_t)sd.x * 256 + l * 8);
        float2 p0 = f8x2tof2((unsigned short)(raw.x & 0xffffu));
        float2 p1 = f8x2tof2((unsigned short)(raw.x >> 16));
        float2 p2 = f8x2tof2((unsigned short)(raw.y & 0xffffu));
        float2 p3 = f8x2tof2((unsigned short)(raw.y >> 16));
        a0 = fmaf(w, p0.x, a0); a1 = fmaf(w, p0.y, a1);
        a2 = fmaf(w, p1.x, a2); a3 = fmaf(w, p1.y, a3);
        a4 = fmaf(w, p2.x, a4); a5 = fmaf(w, p2.y, a5);
        a6 = fmaf(w, p3.x, a6); a7 = fmaf(w, p3.y, a7);
        swa += w;
    }
    a0 += c0; a1 += c1; a2 += c2; a3 += c3;
    a4 += c4; a5 += c5; a6 += c6; a7 += c7;
    float sw = swa + swb;
    float inv = 1.f / (sw + 1e-16f);
    const float4* b4 = reinterpret_cast<const float4*>(b1);
    float4 ba = b4[l * 2], bb = b4[l * 2 + 1];
    float o0 = eluf(a0 * inv + ba.x), o1 = eluf(a1 * inv + ba.y);
    float o2 = eluf(a2 * inv + ba.z), o3 = eluf(a3 * inv + ba.w);
    float o4 = eluf(a4 * inv + bb.x), o5 = eluf(a5 * inv + bb.y);
    float o6 = eluf(a6 * inv + bb.z), o7 = eluf(a7 * inv + bb.w);
    uint4 outw;
    *reinterpret_cast<__nv_bfloat162*>(&outw.x) = __floats2bfloat162_rn(o0, o1);
    *reinterpret_cast<__nv_bfloat162*>(&outw.y) = __floats2bfloat162_rn(o2, o3);
    *reinterpret_cast<__nv_bfloat162*>(&outw.z) = __floats2bfloat162_rn(o4, o5);
    *reinterpret_cast<__nv_bfloat162*>(&outw.w) = __floats2bfloat162_rn(o6, o7);
    *reinterpret_cast<uint4*>(g_h1b + (size_t)node * 256 + l * 8) = outw;
}

// ---- xw2 = h1 @ W2 via packed f32x2 FMA. 64 nodes/block, bf16 store ----
#define XW2_NODES 64
__global__ void k_xw2(const float* __restrict__ W2, const float* __restrict__ as2,
                      const float* __restrict__ ad2, int n) {
    extern __shared__ float sm[];
    float* sWx = sm;                 // 32KB: [kq*128 + 4l + c] = W2[(4kq+c)*64 + 2l]
    float* sWy = sm + 8192;          // 32KB: same, col 2l+1
    float* srow = sm + 16384;        // 64KB: 64 rows x 256 fp32
    int t = threadIdx.x;             // 256 threads
    int l = t & 31;
    {
        const float2* w2v = reinterpret_cast<const float2*>(W2);
        for (int k = t >> 5; k < 256; k += 8) {
            float2 w = w2v[k * 32 + l];          // (W2[k][2l], W2[k][2l+1]) coalesced
            int a = (k >> 2) * 128 + l * 4 + (k & 3);
            sWx[a] = w.x;
            sWy[a] = w.y;
        }
    }
    int base = blockIdx.x * XW2_NODES;
    int cnt = min(XW2_NODES, n - base);
    {
        const uint4* h4 = reinterpret_cast<const uint4*>(g_h1b + (size_t)base * 256);
        for (int i = t; i < cnt * 32; i += 256) {
            uint4 raw = h4[i];
            float* dp = srow + i * 8;
            float2 p0 = __bfloat1622float2(*reinterpret_cast<__nv_bfloat162*>(&raw.x));
            float2 p1 = __bfloat1622float2(*reinterpret_cast<__nv_bfloat162*>(&raw.y));
            float2 p2 = __bfloat1622float2(*reinterpret_cast<__nv_bfloat162*>(&raw.z));
            float2 p3 = __bfloat1622float2(*reinterpret_cast<__nv_bfloat162*>(&raw.w));
            dp[0] = p0.x; dp[1] = p0.y; dp[2] = p1.x; dp[3] = p1.y;
            dp[4] = p2.x; dp[5] = p2.y; dp[6] = p3.x; dp[7] = p3.y;
        }
        for (int i = cnt * 32 + t; i < XW2_NODES * 32; i += 256) {
            float4* dp = reinterpret_cast<float4*>(srow + i * 8);
            dp[0] = make_float4(0, 0, 0, 0);
            dp[1] = make_float4(0, 0, 0, 0);
        }
    }
    __syncthreads();
    int warp = t >> 5;
    int nb = warp * 8;
    const float4* wx4 = reinterpret_cast<const float4*>(sWx);
    const float4* wy4 = reinterpret_cast<const float4*>(sWy);
    const float4* sr4 = reinterpret_cast<const float4*>(srow);
    float2 A0[8], A1[8];
#pragma unroll
    for (int j = 0; j < 8; j++) { A0[j] = make_float2(0, 0); A1[j] = make_float2(0, 0); }
#pragma unroll 2
    for (int kq = 0; kq < 64; kq++) {
        float4 wx = wx4[kq * 32 + l];
        float4 wy = wy4[kq * 32 + l];
        float2 wx01 = make_float2(wx.x, wx.y), wx23 = make_float2(wx.z, wx.w);
        float2 wy01 = make_float2(wy.x, wy.y), wy23 = make_float2(wy.z, wy.w);
#pragma unroll
        for (int j = 0; j < 8; j++) {
            float4 h = sr4[(nb + j) * 64 + kq];
            float2 h01 = make_float2(h.x, h.y), h23 = make_float2(h.z, h.w);
            ffma2(A0[j], h01, wx01);
            ffma2(A0[j], h23, wx23);
            ffma2(A1[j], h01, wy01);
            ffma2(A1[j], h23, wy23);
        }
    }
    float s0 = as2[2 * l], s1 = as2[2 * l + 1];
    float d0 = ad2[2 * l], d1 = ad2[2 * l + 1];
#pragma unroll
    for (int j = 0; j < 8; j++) {
        float a0 = A0[j].x + A0[j].y;
        float a1 = A1[j].x + A1[j].y;
        int node = base + nb + j;
        bool ok = node < n;
        if (ok) {
            *reinterpret_cast<__nv_bfloat162*>(g_xw2b + (size_t)node * 64 + 2 * l) =
                __floats2bfloat162_rn(a0, a1);
        }
        float vs = a0 * s0 + a1 * s1;
        float vd = a0 * d0 + a1 * d1;
#pragma unroll
        for (int o = 16; o; o >>= 1) {
            vs += __shfl_down_sync(0xffffffffu, vs, o);
            vd += __shfl_down_sync(0xffffffffu, vd, o);
        }
        if (l == 0 && ok) { g_als2[node] = vs; g_ald2[node] = vd; }
    }
}

// ---- conv2 gather + fused attention + fused cluster pooling, int4 slot pairs ----
__global__ void k_gather2(const int* __restrict__ assign, int n) {
    __shared__ float sval[64 * 65];
    __shared__ int   sa[64];
    int t = threadIdx.x;            // 1024 threads, 64 nodes/block
    int nl = t >> 4;
    int c = t & 15;
    int node = blockIdx.x * 64 + nl;
    float4 accA = make_float4(0, 0, 0, 0);
    float4 accB = make_float4(0, 0, 0, 0);
    if (node < n) {
        int beg = g_off[node], end = g_off[node + 1];
        float aldv = g_ald2[node];
        float ce4 = g_ce[4];
        float swa = 0.f, swb = 0.f;
        int i = beg;
        if ((i & 1) && i < end) {
            int2 sd = g_slot[i];
            float w = __expf(lrelu(g_als2[sd.x] + aldv + __int_as_float(sd.y) * ce4));
            uint2 raw = *reinterpret_cast<const uint2*>(g_xw2b + (size_t)sd.x * 64 + c * 4);
            float2 p0 = __bfloat1622float2(*reinterpret_cast<__nv_bfloat162*>(&raw.x));
            float2 p1 = __bfloat1622float2(*reinterpret_cast<__nv_bfloat162*>(&raw.y));
            accA.x = fmaf(w, p0.x, accA.x); accA.y = fmaf(w, p0.y, accA.y);
            accA.z = fmaf(w, p1.x, accA.z); accA.w = fmaf(w, p1.y, accA.w);
            swa += w;
            i++;
        }
        for (; i + 2 <= end; i += 2) {
            int4 ss = *reinterpret_cast<const int4*>(&g_slot[i]);
            float lgA = g_als2[ss.x] + aldv + __int_as_float(ss.y) * ce4;
            float lgB = g_als2[ss.z] + aldv + __int_as_float(ss.w) * ce4;
            uint2 rA = *reinterpret_cast<const uint2*>(g_xw2b + (size_t)ss.x * 64 + c * 4);
            uint2 rB = *reinterpret_cast<const uint2*>(g_xw2b + (size_t)ss.z * 64 + c * 4);
            float wA = __expf(lrelu(lgA));
            float wB = __expf(lrelu(lgB));
            float2 pA0 = __bfloat1622float2(*reinterpret_cast<__nv_bfloat162*>(&rA.x));
            float2 pA1 = __bfloat1622float2(*reinterpret_cast<__nv_bfloat162*>(&rA.y));
            float2 pB0 = __bfloat1622float2(*reinterpret_cast<__nv_bfloat162*>(&rB.x));
            float2 pB1 = __bfloat1622float2(*reinterpret_cast<__nv_bfloat162*>(&rB.y));
            accA.x = fmaf(wA, pA0.x, accA.x); accA.y = fmaf(wA, pA0.y, accA.y);
            accA.z = fmaf(wA, pA1.x, accA.z); accA.w = fmaf(wA, pA1.y, accA.w);
            accB.x = fmaf(wB, pB0.x, accB.x); accB.y = fmaf(wB, pB0.y, accB.y);
            accB.z = fmaf(wB, pB1.x, accB.z); accB.w = fmaf(wB, pB1.y, accB.w);
            swa += wA; swb += wB;
        }
        if (i < end) {
            int2 sd = g_slot[i];
            float w = __expf(lrelu(g_als2[sd.x] + aldv + __int_as_float(sd.y) * ce4));
            uint2 raw = *reinterpret_cast<const uint2*>(g_xw2b + (size_t)sd.x * 64 + c * 4);
            float2 p0 = __bfloat1622float2(*reinterpret_cast<__nv_bfloat162*>(&raw.x));
            float2 p1 = __bfloat1622float2(*reinterpret_cast<__nv_bfloat162*>(&raw.y));
            accA.x = fmaf(w, p0.x, accA.x); accA.y = fmaf(w, p0.y, accA.y);
            accA.z = fmaf(w, p1.x, accA.z); accA.w = fmaf(w, p1.y, accA.w);
            swa += w;
        }
        accA.x += accB.x; accA.y += accB.y; accA.z += accB.z; accA.w += accB.w;
        float inv = 1.f / (swa + swb + 1e-16f);
        accA.x *= inv; accA.y *= inv; accA.z *= inv; accA.w *= inv;
        if (c == 0) sa[nl] = assign[node];
    } else if (c == 0) {
        sa[nl] = -1;
    }
    float* vp = &sval[nl * 65 + c * 4];
    vp[0] = accA.x; vp[1] = accA.y; vp[2] = accA.z; vp[3] = accA.w;
    __syncthreads();
    if (t < 256) {
        int k = t >> 6, ch = t & 63;
        float s = 0.f;
        for (int j = 0; j < 64; j++) {
            float v = sval[j * 65 + ch];
            if (sa[j] == k) s += v;
        }
        if (s != 0.f) atomicAdd(&g_pool[k * 64 + ch], s);
    }
}

// ---- final: means + MLP + softmax + output; zeroes g_pool for next replay ----
__global__ void k_final(const float* __restrict__ b2, const float* __restrict__ A1,
                        const float* __restrict__ c1, const float* __restrict__ A2,
                        const float* __restrict__ c2, float* __restrict__ out) {
    __shared__ float z[4][64];
    __shared__ float red[64];
    __shared__ float logits[4];
    __shared__ float probs[4];
    int t = threadIdx.x;
    float cf[4];
#pragma unroll
    for (int k = 0; k < 4; k++) {
        float cn = g_pool[256 + k];
        z[k][t] = (cn > 0.f) ? (g_pool[k * 64 + t] / cn + b2[t]) : 0.f;
        cf[k] = (cn > 0.f) ? (g_pool[260 + k] / cn) : 0.f;
    }
    __syncthreads();
    // cleanup for next replay (all values already consumed into z/cf)
#pragma unroll
    for (int k = 0; k < 4; k++) g_pool[k * 64 + t] = 0.f;
    if (t < 8) g_pool[256 + t] = 0.f;
    for (int k = 0; k < 4; k++) {
        float acc = c1[t];
        for (int i = 0; i < 64; i++) acc = fmaf(z[k][i], A1[i * 64 + t], acc);
        acc = fmaf(cf[k], A1[64 * 64 + t], acc);
        acc = fmaxf(acc, 0.f) * A2[t];
        red[t] = acc;
        __syncthreads();
        if (t == 0) {
            float s = 0.f;
            for (int i = 0; i < 64; i++) s += red[i];
            logits[k] = s + c2[0];
        }
        __syncthreads();
    }
    if (t == 0) {
        float m = fmaxf(fmaxf(logits[0], logits[1]), fmaxf(logits[2], logits[3]));
        float e0 = expf(logits[0] - m), e1 = expf(logits[1] - m);
        float e2 = expf(logits[2] - m), e3 = expf(logits[3] - m);
        float inv = 1.f / (e0 + e1 + e2 + e3);
        probs[0] = e0 * inv; probs[1] = e1 * inv; probs[2] = e2 * inv; probs[3] = e3 * inv;
    }
    __syncthreads();
    if (t < 4) out[t] = probs[t];
#pragma unroll
    for (int k = 0; k < 4; k++) out[4 + k * 64 + t] = z[k][t];
}

extern "C" void kernel_launch(void* const* d_in, const int* in_sizes, int n_in,
                              void* d_out, int out_size) {
    const float* x    = (const float*)d_in[0];
    const int*   ei   = (const int*)d_in[1];
    const float* ea   = (const float*)d_in[2];
    const int*   assign = (const int*)d_in[3];
    const float* W1   = (const float*)d_in[4];
    const float* as1  = (const float*)d_in[5];
    const float* ad1  = (const float*)d_in[6];
    const float* We1  = (const float*)d_in[7];
    const float* ae1  = (const float*)d_in[8];
    const float* b1   = (const float*)d_in[9];
    const float* W2   = (const float*)d_in[10];
    const float* as2  = (const float*)d_in[11];
    const float* ad2  = (const float*)d_in[12];
    const float* We2  = (const float*)d_in[13];
    const float* ae2  = (const float*)d_in[14];
    const float* b2   = (const float*)d_in[15];
    const float* A1   = (const float*)d_in[16];
    const float* c1   = (const float*)d_in[17];
    const float* A2   = (const float*)d_in[18];
    const float* c2   = (const float*)d_in[19];
    float* out = (float*)d_out;

    int n = in_sizes[0] / 7;
    int e = in_sizes[2];
    const int* src = ei;
    const int* dst = ei + e;
    int tot = e + n;
    int nb = (n + SCAN_CHUNK - 1) / SCAN_CHUNK;

    // side stream + events for overlapping xw1 with the CSR-build chain
    static cudaStream_t sB = nullptr;
    static cudaEvent_t evFork = nullptr, evJoin = nullptr;
    if (sB == nullptr) {
        cudaStreamCreateWithFlags(&sB, cudaStreamNonBlocking);
        cudaEventCreateWithFlags(&evFork, cudaEventDisableTiming);
        cudaEventCreateWithFlags(&evJoin, cudaEventDisableTiming);
    }

    cudaEventRecord(evFork, 0);
    cudaStreamWaitEvent(sB, evFork, 0);
    k_xw1<<<(n + 7) / 8, 256, 0, sB>>>(x, W1, as1, ad1, n);
    cudaEventRecord(evJoin, sB);

    k_degloop<<<(tot + 255) / 256, 256>>>(dst, ea, x, assign, We1, ae1, We2, ae2, e, n);
    k_part<<<nb, 256>>>(n);
    k_offs<<<nb, 256>>>(n, tot, nb);
    k_fill<<<(tot + 255) / 256, 256>>>(src, dst, ea, e, n);

    cudaStreamWaitEvent(0, evJoin, 0);
    k_gather1<<<(n * 32 + 255) / 256, 256>>>(b1, n);

    cudaFuncSetAttribute(k_xw2, cudaFuncAttributeMaxDynamicSharedMemorySize, 131072);
    k_xw2<<<(n + XW2_NODES - 1) / XW2_NODES, 256, 131072>>>(W2, as2, ad2, n);

    k_gather2<<<(n + 63) / 64, 1024>>>(assign, n);
    k_final<<<1, 64>>>(b2, A1, c1, A2, c2, out);
}

// round 15
// speedup vs baseline: 1.2080x; 1.2080x over previous
#include <cuda_runtime.h>
#include <cuda_bf16.h>
#include <cuda_fp8.h>
#include <math.h>
#include <cstdint>

#define MAXN 50048
#define MAXE 800000
#define MAXT (MAXE + MAXN)
#define SCAN_CHUNK 1024
#define EA_SCALE 268435456.0f   // 2^28

// ---- scratch (static __device__, no allocations) ----
__device__ __align__(16) unsigned char g_xw1f8[MAXN * 256];
__device__ __align__(16) float g_als1[MAXN * 4];
__device__ __align__(16) float g_ald1[MAXN * 4];
__device__ unsigned long long g_dl[MAXN];   // (count<<40) | fixed-point ea sum
__device__ int   g_off[MAXN + 1];
__device__ int   g_cur[MAXN];
__device__ __align__(16)  int2  g_slot[MAXT];    // (src, ea-bits) per adjacency slot
__device__ int   g_bsum[64];
__device__ __align__(16) __nv_bfloat16 g_h1b[MAXN * 256];
__device__ __align__(16) __nv_bfloat16 g_xw2b[MAXN * 64];
__device__ float g_als2[MAXN];
__device__ float g_ald2[MAXN];
__device__ float g_ce[5];
__device__ float g_pool[264];   // [0:256) zsum[4][64], [256:260) cnt, [260:264) cf

__device__ __forceinline__ float lrelu(float x) { return x > 0.f ? x : 0.2f * x; }
__device__ __forceinline__ float eluf(float x)  { return x > 0.f ? x : (expf(x) - 1.f); }

__device__ __forceinline__ float2 f8x2tof2(unsigned short v) {
    __half2_raw hr = __nv_cvt_fp8x2_to_halfraw2((__nv_fp8x2_storage_t)v, __NV_E4M3);
    return __half22float2(*reinterpret_cast<__half2*>(&hr));
}
__device__ __forceinline__ unsigned short f2tof8x2(float a, float b) {
    return (unsigned short)__nv_cvt_float2_to_fp8x2(make_float2(a, b),
                                                    __NV_SATFINITE, __NV_E4M3);
}

// ---- degree+ea-sum (single packed 64-bit atomic) + cluster cnt/cf + ce ----
__global__ void k_degloop(const int* __restrict__ dst, const float* __restrict__ ea,
                          const float* __restrict__ x, const int* __restrict__ assign,
                          const float* __restrict__ We1, const float* __restrict__ ae1,
                          const float* __restrict__ We2, const float* __restrict__ ae2,
                          int e, int n) {
    __shared__ float s8[8];
    int t = threadIdx.x;
    if (t < 8) s8[t] = 0.f;
    __syncthreads();
    int idx = blockIdx.x * blockDim.x + t;
    if (idx < e) {
        int d = dst[idx];
        unsigned long long pk = (1ULL << 40) |
            (unsigned long long)(unsigned int)__float2uint_rn(ea[idx] * EA_SCALE);
        atomicAdd(&g_dl[d], pk);
    } else if (idx < e + n) {
        int node = idx - e;
        atomicAdd(&g_dl[node], 1ULL << 40);
        int a = assign[node];
        atomicAdd(&s8[a], 1.f);
        atomicAdd(&s8[4 + a], x[node * 7 + 6]);
    }
    if (blockIdx.x == 0) {
        __shared__ float s5[5];
        if (t < 5) s5[t] = 0.f;
        __syncthreads();
        atomicAdd(&s5[t >> 6], We1[t] * ae1[t]);
        if (t < 64) atomicAdd(&s5[4], We2[t] * ae2[t]);
        __syncthreads();
        if (t < 5) g_ce[t] = s5[t];
    }
    __syncthreads();
    if (t < 8 && s8[t] != 0.f) atomicAdd(&g_pool[256 + t], s8[t]);
}

// ---- scan stage 1: per-block sums (256 thr x 4 elems = 1024/block) ----
__global__ void k_part(int n) {
    int t = threadIdx.x;
    int base = blockIdx.x * SCAN_CHUNK + t * 4;
    int s = 0;
#pragma unroll
    for (int i = 0; i < 4; i++) {
        int idx = base + i;
        if (idx < n) s += (int)(g_dl[idx] >> 40);
    }
#pragma unroll
    for (int o = 16; o; o >>= 1) s += __shfl_down_sync(0xffffffffu, s, o);
    __shared__ int ws[8];
    if ((t & 31) == 0) ws[t >> 5] = s;
    __syncthreads();
    if (t < 8) {
        int v = ws[t];
#pragma unroll
        for (int o = 4; o; o >>= 1) v += __shfl_down_sync(0xffu, v, o);
        if (t == 0) g_bsum[blockIdx.x] = v;
    }
}

// ---- scan stage 2: block-local scan + inline 64-wide scan of block sums ----
__global__ void k_offs(int n, int tot, int nb) {
    int t = threadIdx.x;                      // 256 threads
    __shared__ int spre[64];
    __shared__ int w0tot;
    if (t < 64) {
        int s = (t < nb) ? g_bsum[t] : 0;
        int lane = t & 31;
        int v = s;
#pragma unroll
        for (int o = 1; o < 32; o <<= 1) {
            int u = __shfl_up_sync(0xffffffffu, v, o);
            if (lane >= o) v += u;
        }
        if (t == 31) w0tot = v;
        spre[t] = v - s;                      // warp-local exclusive; fix warp1 below
    }
    __syncthreads();
    if (t >= 32 && t < 64) spre[t] += w0tot;
    int base = blockIdx.x * SCAN_CHUNK + t * 4;
    int v[4];
    int s = 0;
#pragma unroll
    for (int i = 0; i < 4; i++) {
        int idx = base + i;
        v[i] = (idx < n) ? (int)(g_dl[idx] >> 40) : 0;
        s += v[i];
    }
    int lane = t & 31, w = t >> 5;
    int ps = s;
#pragma unroll
    for (int o = 1; o < 32; o <<= 1) {
        int u = __shfl_up_sync(0xffffffffu, ps, o);
        if (lane >= o) ps += u;
    }
    __shared__ int ws[8];
    if (lane == 31) ws[w] = ps;
    __syncthreads();
    if (t < 8) {
        int x = ws[t];
#pragma unroll
        for (int o = 1; o < 8; o <<= 1) {
            int u = __shfl_up_sync(0xffu, x, o);
            if (t >= o) x += u;
        }
        ws[t] = x;
    }
    __syncthreads();
    int excl = ps - s + (w ? ws[w - 1] : 0) + spre[blockIdx.x];
#pragma unroll
    for (int i = 0; i < 4; i++) {
        int idx = base + i;
        if (idx < n) {
            g_off[idx] = excl;
            g_cur[idx] = excl;
            excl += v[i];
        }
    }
    if (blockIdx.x == 0 && t == 0) g_off[n] = tot;
}

// ---- xw1 = x @ W1 (+ fused al_src1 / al_dst1), one warp per node, fp8 store ----
__global__ void k_xw1(const float* __restrict__ x, const float* __restrict__ W1,
                      const float* __restrict__ as1, const float* __restrict__ ad1, int n) {
    __shared__ float sW[7 * 256];
    __shared__ float sA[256];
    __shared__ float sB[256];
    int t = threadIdx.x;
    for (int i = t; i < 7 * 256; i += blockDim.x) sW[i] = W1[i];
    if (t < 256) { sA[t] = as1[t]; sB[t] = ad1[t]; }
    __syncthreads();
    int node = (blockIdx.x * blockDim.x + t) >> 5;
    int lane = t & 31;
    if (node >= n) return;
    float xv[7];
#pragma unroll
    for (int i = 0; i < 7; i++) xv[i] = x[node * 7 + i];
    const float2* sW2 = reinterpret_cast<const float2*>(sW);
    const float2* sA2 = reinterpret_cast<const float2*>(sA);
    const float2* sB2 = reinterpret_cast<const float2*>(sB);
    float accs[4], accd[4];
    unsigned short* ob = reinterpret_cast<unsigned short*>(g_xw1f8 + (size_t)node * 256);
#pragma unroll
    for (int k = 0; k < 4; k++) {
        int p = k * 32 + lane;                 // pair index within 128-wide row
        float v0 = 0.f, v1 = 0.f;
#pragma unroll
        for (int i = 0; i < 7; i++) {
            float2 wv = sW2[i * 128 + p];
            v0 = fmaf(xv[i], wv.x, v0);
            v1 = fmaf(xv[i], wv.y, v1);
        }
        float2 av = sA2[p], bv = sB2[p];
        accs[k] = fmaf(v0, av.x, v1 * av.y);
        accd[k] = fmaf(v0, bv.x, v1 * bv.y);
        ob[p] = f2tof8x2(v0, v1);
    }
#pragma unroll
    for (int h = 0; h < 4; h++) {
        float vs = accs[h], vd = accd[h];
#pragma unroll
        for (int o = 16; o; o >>= 1) {
            vs += __shfl_down_sync(0xffffffffu, vs, o);
            vd += __shfl_down_sync(0xffffffffu, vd, o);
        }
        if (lane == 0) { g_als1[node * 4 + h] = vs; g_ald1[node * 4 + h] = vd; }
    }
}

// ---- fill adjacency; self-loop threads decode a and re-zero g_dl for next run ----
__global__ void k_fill(const int* __restrict__ src, const int* __restrict__ dst,
                       const float* __restrict__ ea, int e, int n) {
    int idx = blockIdx.x * blockDim.x + threadIdx.x;
    if (idx >= e + n) return;
    int d, s; float a;
    if (idx < e) { d = dst[idx]; s = src[idx]; a = ea[idx]; }
    else {
        d = idx - e; s = d;
        unsigned long long v = g_dl[d];
        float cnt = (float)(int)((v >> 40) - 1ULL);
        float sum = (float)(v & ((1ULL << 40) - 1ULL)) * (1.0f / EA_SCALE);
        a = sum / fmaxf(cnt, 1.f);
        g_dl[d] = 0ULL;          // cleanup for next launch
    }
    int p = atomicAdd(&g_cur[d], 1);
    g_slot[p] = make_int2(s, __float_as_int(a));
}

// ---- conv1 gather-aggregate, 32 thr/node, fp8 rows, int4 slot pairs ----
__global__ void k_gather1(const float* __restrict__ b1, int n) {
    int gt = blockIdx.x * blockDim.x + threadIdx.x;
    int node = gt >> 5;
    if (node >= n) return;
    int l = gt & 31, h = l >> 3;
    int beg = g_off[node], end = g_off[node + 1];
    float ald_h = g_ald1[node * 4 + h];
    float ce_h = g_ce[h];
    float a0 = 0, a1 = 0, a2 = 0, a3 = 0, a4 = 0, a5 = 0, a6 = 0, a7 = 0;
    float c0 = 0, c1 = 0, c2 = 0, c3 = 0, c4 = 0, c5 = 0, c6 = 0, c7 = 0;
    float swa = 0.f, swb = 0.f;
    int i = beg;
    // peel to 16B-aligned pair boundary
    if ((i & 1) && i < end) {
        int2 sd = g_slot[i];
        float lg = g_als1[sd.x * 4 + h] + ald_h + __int_as_float(sd.y) * ce_h;
        float w = __expf(lrelu(lg));
        uint2 raw = *reinterpret_cast<const uint2*>(g_xw1f8 + (size_t)sd.x * 256 + l * 8);
        float2 p0 = f8x2tof2((unsigned short)(raw.x & 0xffffu));
        float2 p1 = f8x2tof2((unsigned short)(raw.x >> 16));
        float2 p2 = f8x2tof2((unsigned short)(raw.y & 0xffffu));
        float2 p3 = f8x2tof2((unsigned short)(raw.y >> 16));
        a0 = fmaf(w, p0.x, a0); a1 = fmaf(w, p0.y, a1);
        a2 = fmaf(w, p1.x, a2); a3 = fmaf(w, p1.y, a3);
        a4 = fmaf(w, p2.x, a4); a5 = fmaf(w, p2.y, a5);
        a6 = fmaf(w, p3.x, a6); a7 = fmaf(w, p3.y, a7);
        swa += w;
        i++;
    }
    for (; i + 2 <= end; i += 2) {
        int4 ss = *reinterpret_cast<const int4*>(&g_slot[i]);
        float lgA = g_als1[ss.x * 4 + h] + ald_h + __int_as_float(ss.y) * ce_h;
        float lgB = g_als1[ss.z * 4 + h] + ald_h + __int_as_float(ss.w) * ce_h;
        uint2 rA = *reinterpret_cast<const uint2*>(g_xw1f8 + (size_t)ss.x * 256 + l * 8);
        uint2 rB = *reinterpret_cast<const uint2*>(g_xw1f8 + (size_t)ss.z * 256 + l * 8);
        float wA = __expf(lrelu(lgA));
        float wB = __expf(lrelu(lgB));
        float2 pA0 = f8x2tof2((unsigned short)(rA.x & 0xffffu));
        float2 pA1 = f8x2tof2((unsigned short)(rA.x >> 16));
        float2 pA2 = f8x2tof2((unsigned short)(rA.y & 0xffffu));
        float2 pA3 = f8x2tof2((unsigned short)(rA.y >> 16));
        float2 pB0 = f8x2tof2((unsigned short)(rB.x & 0xffffu));
        float2 pB1 = f8x2tof2((unsigned short)(rB.x >> 16));
        float2 pB2 = f8x2tof2((unsigned short)(rB.y & 0xffffu));
        float2 pB3 = f8x2tof2((unsigned short)(rB.y >> 16));
        a0 = fmaf(wA, pA0.x, a0); a1 = fmaf(wA, pA0.y, a1);
        a2 = fmaf(wA, pA1.x, a2); a3 = fmaf(wA, pA1.y, a3);
        a4 = fmaf(wA, pA2.x, a4); a5 = fmaf(wA, pA2.y, a5);
        a6 = fmaf(wA, pA3.x, a6); a7 = fmaf(wA, pA3.y, a7);
        c0 = fmaf(wB, pB0.x, c0); c1 = fmaf(wB, pB0.y, c1);
        c2 = fmaf(wB, pB1.x, c2); c3 = fmaf(wB, pB1.y, c3);
        c4 = fmaf(wB, pB2.x, c4); c5 = fmaf(wB, pB2.y, c5);
        c6 = fmaf(wB, pB3.x, c6); c7 = fmaf(wB, pB3.y, c7);
        swa += wA; swb += wB;
    }
    if (i < end) {
        int2 sd = g_slot[i];
        float lg = g_als1[sd.x * 4 + h] + ald_h + __int_as_float(sd.y) * ce_h;
        float w = __expf(lrelu(lg));
        uint2 raw = *reinterpret_cast<const uint2*>(g_xw1f8 + (size_t)sd.x * 256 + l * 8);
        float2 p0 = f8x2tof2((unsigned short)(raw.x & 0xffffu));
        float2 p1 = f8x2tof2((unsigned short)(raw.x >> 16));
        float2 p2 = f8x2tof2((unsigned short)(raw.y & 0xffffu));
        float2 p3 = f8x2tof2((unsigned short)(raw.y >> 16));
        a0 = fmaf(w, p0.x, a0); a1 = fmaf(w, p0.y, a1);
        a2 = fmaf(w, p1.x, a2); a3 = fmaf(w, p1.y, a3);
        a4 = fmaf(w, p2.x, a4); a5 = fmaf(w, p2.y, a5);
        a6 = fmaf(w, p3.x, a6); a7 = fmaf(w, p3.y, a7);
        swa += w;
    }
    a0 += c0; a1 += c1; a2 += c2; a3 += c3;
    a4 += c4; a5 += c5; a6 += c6; a7 += c7;
    float sw = swa + swb;
    float inv = 1.f / (sw + 1e-16f);
    const float4* b4 = reinterpret_cast<const float4*>(b1);
    float4 ba = b4[l * 2], bb = b4[l * 2 + 1];
    float o0 = eluf(a0 * inv + ba.x), o1 = eluf(a1 * inv + ba.y);
    float o2 = eluf(a2 * inv + ba.z), o3 = eluf(a3 * inv + ba.w);
    float o4 = eluf(a4 * inv + bb.x), o5 = eluf(a5 * inv + bb.y);
    float o6 = eluf(a6 * inv + bb.z), o7 = eluf(a7 * inv + bb.w);
    uint4 outw;
    *reinterpret_cast<__nv_bfloat162*>(&outw.x) = __floats2bfloat162_rn(o0, o1);
    *reinterpret_cast<__nv_bfloat162*>(&outw.y) = __floats2bfloat162_rn(o2, o3);
    *reinterpret_cast<__nv_bfloat162*>(&outw.z) = __floats2bfloat162_rn(o4, o5);
    *reinterpret_cast<__nv_bfloat162*>(&outw.w) = __floats2bfloat162_rn(o6, o7);
    *reinterpret_cast<uint4*>(g_h1b + (size_t)node * 256 + l * 8) = outw;
}

// ---- xw2 = h1 @ W2 via m16n8k16 bf16 HMMA with W2 hi/lo split (fp32-accurate) ----
// 8 warps x 16 nodes = 128 nodes/block. W2^T staged hi+lo bf16, stride 264
// (bank = 4g+tig: conflict-free). Dynamic smem 68096 B.
#define W2T_STRIDE 264
__global__ void __launch_bounds__(256) k_xw2_hmma(
    const float* __restrict__ W2, const float* __restrict__ as2,
    const float* __restrict__ ad2, int n) {
    extern __shared__ char smraw[];
    __nv_bfloat16* sWhi = reinterpret_cast<__nv_bfloat16*>(smraw);
    __nv_bfloat16* sWlo = reinterpret_cast<__nv_bfloat16*>(smraw + 33792);
    float* sAt = reinterpret_cast<float*>(smraw + 67584);   // (as2, ad2) pairs
    int t = threadIdx.x;
    for (int i = t; i < 16384; i += 256) {
        int k = i >> 6, c = i & 63;                 // W2[k][c], coalesced read
        float w = W2[i];
        __nv_bfloat16 hi = __float2bfloat16(w);
        __nv_bfloat16 lo = __float2bfloat16(w - __bfloat162float(hi));
        sWhi[c * W2T_STRIDE + k] = hi;
        sWlo[c * W2T_STRIDE + k] = lo;
    }
    if (t < 64) { sAt[2 * t] = as2[t]; sAt[2 * t + 1] = ad2[t]; }
    __syncthreads();
    int warp = t >> 5, lane = t & 31;
    int g = lane >> 2, tig = lane & 3;
    int row0 = blockIdx.x * 128 + warp * 16 + g;    // fragment rows g / g+8
    int row1 = row0 + 8;
    bool ok0 = row0 < n, ok1 = row1 < n;
    const char* r0p = reinterpret_cast<const char*>(g_h1b + (size_t)(ok0 ? row0 : 0) * 256);
    const char* r1p = reinterpret_cast<const char*>(g_h1b + (size_t)(ok1 ? row1 : 0) * 256);
    float acc[8][4];
#pragma unroll
    for (int nt = 0; nt < 8; nt++)
#pragma unroll
        for (int j = 0; j < 4; j++) acc[nt][j] = 0.f;
#pragma unroll 2
    for (int ks = 0; ks < 16; ks++) {
        int kc = ks * 16 + tig * 2;                 // bf16 col index
        uint32_t a0 = 0, a1 = 0, a2 = 0, a3 = 0;
        if (ok0) {
            a0 = *reinterpret_cast<const uint32_t*>(r0p + kc * 2);
            a2 = *reinterpret_cast<const uint32_t*>(r0p + (kc + 8) * 2);
        }
        if (ok1) {
            a1 = *reinterpret_cast<const uint32_t*>(r1p + kc * 2);
            a3 = *reinterpret_cast<const uint32_t*>(r1p + (kc + 8) * 2);
        }
#pragma unroll
        for (int nt = 0; nt < 8; nt++) {
            int col = nt * 8 + g;
            uint32_t bh0 = *reinterpret_cast<const uint32_t*>(&sWhi[col * W2T_STRIDE + kc]);
            uint32_t bh1 = *reinterpret_cast<const uint32_t*>(&sWhi[col * W2T_STRIDE + kc + 8]);
            uint32_t bl0 = *reinterpret_cast<const uint32_t*>(&sWlo[col * W2T_STRIDE + kc]);
            uint32_t bl1 = *reinterpret_cast<const uint32_t*>(&sWlo[col * W2T_STRIDE + kc + 8]);
            asm volatile(
                "mma.sync.aligned.m16n8k16.row.col.f32.bf16.bf16.f32 "
                "{%0,%1,%2,%3}, {%4,%5,%6,%7}, {%8,%9}, {%0,%1,%2,%3};"
                : "+f"(acc[nt][0]), "+f"(acc[nt][1]), "+f"(acc[nt][2]), "+f"(acc[nt][3])
                : "r"(a0), "r"(a1), "r"(a2), "r"(a3), "r"(bh0), "r"(bh1));
            asm volatile(
                "mma.sync.aligned.m16n8k16.row.col.f32.bf16.bf16.f32 "
                "{%0,%1,%2,%3}, {%4,%5,%6,%7}, {%8,%9}, {%0,%1,%2,%3};"
                : "+f"(acc[nt][0]), "+f"(acc[nt][1]), "+f"(acc[nt][2]), "+f"(acc[nt][3])
                : "r"(a0), "r"(a1), "r"(a2), "r"(a3), "r"(bl0), "r"(bl1));
        }
    }
    // epilogue: c0=(g, nt*8+2tig), c1=(g, +1), c2=(g+8, 2tig), c3=(g+8, +1)
    float vs0 = 0.f, vd0 = 0.f, vs1 = 0.f, vd1 = 0.f;
#pragma unroll
    for (int nt = 0; nt < 8; nt++) {
        int col = nt * 8 + tig * 2;
        float asx = sAt[2 * col], adx = sAt[2 * col + 1];
        float asy = sAt[2 * col + 2], ady = sAt[2 * col + 3];
        vs0 = fmaf(acc[nt][0], asx, fmaf(acc[nt][1], asy, vs0));
        vd0 = fmaf(acc[nt][0], adx, fmaf(acc[nt][1], ady, vd0));
        vs1 = fmaf(acc[nt][2], asx, fmaf(acc[nt][3], asy, vs1));
        vd1 = fmaf(acc[nt][2], adx, fmaf(acc[nt][3], ady, vd1));
    }
#pragma unroll
    for (int o = 1; o < 4; o <<= 1) {
        vs0 += __shfl_xor_sync(0xffffffffu, vs0, o);
        vd0 += __shfl_xor_sync(0xffffffffu, vd0, o);
        vs1 += __shfl_xor_sync(0xffffffffu, vs1, o);
        vd1 += __shfl_xor_sync(0xffffffffu, vd1, o);
    }
    if (tig == 0) {
        if (ok0) { g_als2[row0] = vs0; g_ald2[row0] = vd0; }
        if (ok1) { g_als2[row1] = vs1; g_ald2[row1] = vd1; }
    }
    if (ok0) {
        unsigned int* orow = reinterpret_cast<unsigned int*>(g_xw2b + (size_t)row0 * 64);
#pragma unroll
        for (int nt = 0; nt < 8; nt++) {
            __nv_bfloat162 pv = __floats2bfloat162_rn(acc[nt][0], acc[nt][1]);
            orow[nt * 4 + tig] = *reinterpret_cast<unsigned int*>(&pv);
        }
    }
    if (ok1) {
        unsigned int* orow = reinterpret_cast<unsigned int*>(g_xw2b + (size_t)row1 * 64);
#pragma unroll
        for (int nt = 0; nt < 8; nt++) {
            __nv_bfloat162 pv = __floats2bfloat162_rn(acc[nt][2], acc[nt][3]);
            orow[nt * 4 + tig] = *reinterpret_cast<unsigned int*>(&pv);
        }
    }
}

// ---- conv2 gather + fused attention + fused cluster pooling, int4 slot pairs ----
__global__ void k_gather2(const int* __restrict__ assign, int n) {
    __shared__ float sval[64 * 65];
    __shared__ int   sa[64];
    int t = threadIdx.x;            // 1024 threads, 64 nodes/block
    int nl = t >> 4;
    int c = t & 15;
    int node = blockIdx.x * 64 + nl;
    float4 accA = make_float4(0, 0, 0, 0);
    float4 accB = make_float4(0, 0, 0, 0);
    if (node < n) {
        int beg = g_off[node], end = g_off[node + 1];
        float aldv = g_ald2[node];
        float ce4 = g_ce[4];
        float swa = 0.f, swb = 0.f;
        int i = beg;
        if ((i & 1) && i < end) {
            int2 sd = g_slot[i];
            float w = __expf(lrelu(g_als2[sd.x] + aldv + __int_as_float(sd.y) * ce4));
            uint2 raw = *reinterpret_cast<const uint2*>(g_xw2b + (size_t)sd.x * 64 + c * 4);
            float2 p0 = __bfloat1622float2(*reinterpret_cast<__nv_bfloat162*>(&raw.x));
            float2 p1 = __bfloat1622float2(*reinterpret_cast<__nv_bfloat162*>(&raw.y));
            accA.x = fmaf(w, p0.x, accA.x); accA.y = fmaf(w, p0.y, accA.y);
            accA.z = fmaf(w, p1.x, accA.z); accA.w = fmaf(w, p1.y, accA.w);
            swa += w;
            i++;
        }
        for (; i + 2 <= end; i += 2) {
            int4 ss = *reinterpret_cast<const int4*>(&g_slot[i]);
            float lgA = g_als2[ss.x] + aldv + __int_as_float(ss.y) * ce4;
            float lgB = g_als2[ss.z] + aldv + __int_as_float(ss.w) * ce4;
            uint2 rA = *reinterpret_cast<const uint2*>(g_xw2b + (size_t)ss.x * 64 + c * 4);
            uint2 rB = *reinterpret_cast<const uint2*>(g_xw2b + (size_t)ss.z * 64 + c * 4);
            float wA = __expf(lrelu(lgA));
            float wB = __expf(lrelu(lgB));
            float2 pA0 = __bfloat1622float2(*reinterpret_cast<__nv_bfloat162*>(&rA.x));
            float2 pA1 = __bfloat1622float2(*reinterpret_cast<__nv_bfloat162*>(&rA.y));
            float2 pB0 = __bfloat1622float2(*reinterpret_cast<__nv_bfloat162*>(&rB.x));
            float2 pB1 = __bfloat1622float2(*reinterpret_cast<__nv_bfloat162*>(&rB.y));
            accA.x = fmaf(wA, pA0.x, accA.x); accA.y = fmaf(wA, pA0.y, accA.y);
            accA.z = fmaf(wA, pA1.x, accA.z); accA.w = fmaf(wA, pA1.y, accA.w);
            accB.x = fmaf(wB, pB0.x, accB.x); accB.y = fmaf(wB, pB0.y, accB.y);
            accB.z = fmaf(wB, pB1.x, accB.z); accB.w = fmaf(wB, pB1.y, accB.w);
            swa += wA; swb += wB;
        }
        if (i < end) {
            int2 sd = g_slot[i];
            float w = __expf(lrelu(g_als2[sd.x] + aldv + __int_as_float(sd.y) * ce4));
            uint2 raw = *reinterpret_cast<const uint2*>(g_xw2b + (size_t)sd.x * 64 + c * 4);
            float2 p0 = __bfloat1622float2(*reinterpret_cast<__nv_bfloat162*>(&raw.x));
            float2 p1 = __bfloat1622float2(*reinterpret_cast<__nv_bfloat162*>(&raw.y));
            accA.x = fmaf(w, p0.x, accA.x); accA.y = fmaf(w, p0.y, accA.y);
            accA.z = fmaf(w, p1.x, accA.z); accA.w = fmaf(w, p1.y, accA.w);
            swa += w;
        }
        accA.x += accB.x; accA.y += accB.y; accA.z += accB.z; accA.w += accB.w;
        float inv = 1.f / (swa + swb + 1e-16f);
        accA.x *= inv; accA.y *= inv; accA.z *= inv; accA.w *= inv;
        if (c == 0) sa[nl] = assign[node];
    } else if (c == 0) {
        sa[nl] = -1;
    }
    float* vp = &sval[nl * 65 + c * 4];
    vp[0] = accA.x; vp[1] = accA.y; vp[2] = accA.z; vp[3] = accA.w;
    __syncthreads();
    if (t < 256) {
        int k = t >> 6, ch = t & 63;
        float s = 0.f;
        for (int j = 0; j < 64; j++) {
            float v = sval[j * 65 + ch];
            if (sa[j] == k) s += v;
        }
        if (s != 0.f) atomicAdd(&g_pool[k * 64 + ch], s);
    }
}

// ---- final: means + MLP + softmax + output; zeroes g_pool for next replay ----
__global__ void k_final(const float* __restrict__ b2, const float* __restrict__ A1,
                        const float* __restrict__ c1, const float* __restrict__ A2,
                        const float* __restrict__ c2, float* __restrict__ out) {
    __shared__ float z[4][64];
    __shared__ float red[64];
    __shared__ float logits[4];
    __shared__ float probs[4];
    int t = threadIdx.x;
    float cf[4];
#pragma unroll
    for (int k = 0; k < 4; k++) {
        float cn = g_pool[256 + k];
        z[k][t] = (cn > 0.f) ? (g_pool[k * 64 + t] / cn + b2[t]) : 0.f;
        cf[k] = (cn > 0.f) ? (g_pool[260 + k] / cn) : 0.f;
    }
    __syncthreads();
    // cleanup for next replay (all values already consumed into z/cf)
#pragma unroll
    for (int k = 0; k < 4; k++) g_pool[k * 64 + t] = 0.f;
    if (t < 8) g_pool[256 + t] = 0.f;
    for (int k = 0; k < 4; k++) {
        float acc = c1[t];
        for (int i = 0; i < 64; i++) acc = fmaf(z[k][i], A1[i * 64 + t], acc);
        acc = fmaf(cf[k], A1[64 * 64 + t], acc);
        acc = fmaxf(acc, 0.f) * A2[t];
        red[t] = acc;
        __syncthreads();
        if (t == 0) {
            float s = 0.f;
            for (int i = 0; i < 64; i++) s += red[i];
            logits[k] = s + c2[0];
        }
        __syncthreads();
    }
    if (t == 0) {
        float m = fmaxf(fmaxf(logits[0], logits[1]), fmaxf(logits[2], logits[3]));
        float e0 = expf(logits[0] - m), e1 = expf(logits[1] - m);
        float e2 = expf(logits[2] - m), e3 = expf(logits[3] - m);
        float inv = 1.f / (e0 + e1 + e2 + e3);
        probs[0] = e0 * inv; probs[1] = e1 * inv; probs[2] = e2 * inv; probs[3] = e3 * inv;
    }
    __syncthreads();
    if (t < 4) out[t] = probs[t];
#pragma unroll
    for (int k = 0; k < 4; k++) out[4 + k * 64 + t] = z[k][t];
}

extern "C" void kernel_launch(void* const* d_in, const int* in_sizes, int n_in,
                              void* d_out, int out_size) {
    const float* x    = (const float*)d_in[0];
    const int*   ei   = (const int*)d_in[1];
    const float* ea   = (const float*)d_in[2];
    const int*   assign = (const int*)d_in[3];
    const float* W1   = (const float*)d_in[4];
    const float* as1  = (const float*)d_in[5];
    const float* ad1  = (const float*)d_in[6];
    const float* We1  = (const float*)d_in[7];
    const float* ae1  = (const float*)d_in[8];
    const float* b1   = (const float*)d_in[9];
    const float* W2   = (const float*)d_in[10];
    const float* as2  = (const float*)d_in[11];
    const float* ad2  = (const float*)d_in[12];
    const float* We2  = (const float*)d_in[13];
    const float* ae2  = (const float*)d_in[14];
    const float* b2   = (const float*)d_in[15];
    const float* A1   = (const float*)d_in[16];
    const float* c1   = (const float*)d_in[17];
    const float* A2   = (const float*)d_in[18];
    const float* c2   = (const float*)d_in[19];
    float* out = (float*)d_out;

    int n = in_sizes[0] / 7;
    int e = in_sizes[2];
    const int* src = ei;
    const int* dst = ei + e;
    int tot = e + n;
    int nb = (n + SCAN_CHUNK - 1) / SCAN_CHUNK;

    // side stream + events for overlapping xw1 with the CSR-build chain
    static cudaStream_t sB = nullptr;
    static cudaEvent_t evFork = nullptr, evJoin = nullptr;
    if (sB == nullptr) {
        cudaStreamCreateWithFlags(&sB, cudaStreamNonBlocking);
        cudaEventCreateWithFlags(&evFork, cudaEventDisableTiming);
        cudaEventCreateWithFlags(&evJoin, cudaEventDisableTiming);
        cudaFuncSetAttribute(k_xw2_hmma, cudaFuncAttributeMaxDynamicSharedMemorySize,
                             68096);
    }

    cudaEventRecord(evFork, 0);
    cudaStreamWaitEvent(sB, evFork, 0);
    k_xw1<<<(n + 7) / 8, 256, 0, sB>>>(x, W1, as1, ad1, n);
    cudaEventRecord(evJoin, sB);

    k_degloop<<<(tot + 255) / 256, 256>>>(dst, ea, x, assign, We1, ae1, We2, ae2, e, n);
    k_part<<<nb, 256>>>(n);
    k_offs<<<nb, 256>>>(n, tot, nb);
    k_fill<<<(tot + 255) / 256, 256>>>(src, dst, ea, e, n);

    cudaStreamWaitEvent(0, evJoin, 0);
    k_gather1<<<(n * 32 + 255) / 256, 256>>>(b1, n);

    k_xw2_hmma<<<(n + 127) / 128, 256, 68096>>>(W2, as2, ad2, n);

    k_gather2<<<(n + 63) / 64, 1024>>>(assign, n);
    k_final<<<1, 64>>>(b2, A1, c1, A2, c2, out);
}